// round 4
// baseline (speedup 1.0000x reference)
#include <cuda_runtime.h>
#include <math.h>

// ---------------- scratch (device globals; no mallocs) ----------------
// g_c1 rows padded 28 -> 36 floats so conv2 can do unconditional vector loads.
__device__ float g_c1[2048*32*28*36];   // conv1 out (padded rows)
__device__ float g_c2[2048*64*13*13];   // conv2 out
__device__ float g_c3[2048*64*36];      // conv3 out (N,64,36)
__device__ float g_catt[2048*64];       // channel attention
__device__ float g_tok[2048*36*64];     // tokens (N,36,64) post-CBAM
__device__ float g_qkv[2048*36*192];    // qkv
__device__ float g_attn[2048*36*64];    // attention out (N,36,64)
__device__ float g_h2[2048*2304];       // residual, (N,64,36) flat -> FC input
__device__ float g_feat[2048*256];      // FC out
__device__ float g_gx[2048*384];        // input-side GRU gates
__device__ float g_hid[2048*128];       // GRU hidden per step
__device__ float g_w1t[256*32];         // conv weights transposed: [k][cout]
__device__ float g_w2t[512*64];
__device__ float g_w3t[576*64];
__device__ float g_whht[128*384];       // whh transposed [k][gate]

// ---------------- weight transpose prep ----------------
__global__ void k_transpose(const float* __restrict__ w, int Cout, int K, int which) {
    int idx = blockIdx.x*256 + threadIdx.x;
    if (idx >= Cout*K) return;
    int co = idx / K, k = idx % K;
    float* dst = (which==0) ? g_w1t : (which==1) ? g_w2t : (which==2) ? g_w3t : g_whht;
    dst[k*Cout + co] = w[idx];
}

// ---------------- conv1: (N,4,116,116) -> relu (N,32,28,28pad36), k8 s4 --------
// grid(14, 2048), block 224 (7 warps). 2 oy rows per block.
// thread: cq(8, fastest) x oxq(14); tile 2 ox x 4 cout. Weights staged in smem.
__global__ void __launch_bounds__(224) k_conv1(const float* __restrict__ x,
                                               const float* __restrict__ bias) {
    __shared__ float ws[256*32];     // 32 KB, [k][cout] layout
    {
        const float4* src = (const float4*)g_w1t;
        float4* dst = (float4*)ws;
        #pragma unroll
        for (int i = threadIdx.x; i < 2048; i += 224) dst[i] = src[i];
    }
    __syncthreads();
    int n  = blockIdx.y;
    int oy = blockIdx.x*2 + threadIdx.x/112;
    int t  = threadIdx.x % 112;
    int cq  = t % 8;            // cout quad, fastest for broadcast-friendly LDS
    int oxq = t / 8;            // 0..13 -> ox0 = 2*oxq
    float acc[2][4] = {};
    for (int cin = 0; cin < 4; cin++) {
        const float* xin = x + (size_t)(n*4+cin)*13456 + 4*oy*116 + 8*oxq;
        #pragma unroll
        for (int ky = 0; ky < 8; ky++) {
            const float* xr = xin + ky*116;        // 32B-aligned (8*oxq)
            float xv[12];
            float4 v0 = *(const float4*)(xr);
            float4 v1 = *(const float4*)(xr + 4);
            float4 v2 = *(const float4*)(xr + 8);
            xv[0]=v0.x; xv[1]=v0.y; xv[2]=v0.z; xv[3]=v0.w;
            xv[4]=v1.x; xv[5]=v1.y; xv[6]=v1.z; xv[7]=v1.w;
            xv[8]=v2.x; xv[9]=v2.y; xv[10]=v2.z; xv[11]=v2.w;
            const float* wp = ws + ((cin*8+ky)*8)*32 + 4*cq;
            #pragma unroll
            for (int kx = 0; kx < 8; kx++) {
                float4 wv = *(const float4*)(wp + kx*32);
                float i0 = xv[kx], i1 = xv[kx+4];
                acc[0][0] += i0*wv.x; acc[0][1] += i0*wv.y;
                acc[0][2] += i0*wv.z; acc[0][3] += i0*wv.w;
                acc[1][0] += i1*wv.x; acc[1][1] += i1*wv.y;
                acc[1][2] += i1*wv.z; acc[1][3] += i1*wv.w;
            }
        }
    }
    #pragma unroll
    for (int j = 0; j < 4; j++) {
        int co = cq*4 + j;
        float b = bias[co];
        #pragma unroll
        for (int i = 0; i < 2; i++) {
            float v = acc[i][j] + b;
            g_c1[((size_t)(n*32+co)*28 + oy)*36 + 2*oxq + i] = v > 0.f ? v : 0.f;
        }
    }
}

// ---------------- conv2: (N,32,28pad36) -> relu (N,64,13,13), k4 s2 ------------
// grid(7, 2048), block 224. 2 oy per block (oy=13 clamped+discarded).
// thread: cq(16, fastest) x oxq(7); tile 2 ox x 4 cout (ox=13 discarded).
__global__ void __launch_bounds__(224) k_conv2(const float* __restrict__ bias) {
    int n = blockIdx.y;
    int oy = blockIdx.x*2 + threadIdx.x/112;
    bool oy_ok = (oy < 13); if (!oy_ok) oy = 12;
    int t = threadIdx.x % 112;
    int cq  = t % 16;           // 0..15 -> cout quad
    int oxq = t / 16;           // 0..6 -> ox0 = 2*oxq
    float acc[2][4] = {};
    for (int cin = 0; cin < 32; cin++) {
        const float* xin = g_c1 + (size_t)(n*32+cin)*1008 + 2*oy*36 + 4*oxq;
        #pragma unroll
        for (int ky = 0; ky < 4; ky++) {
            const float* xr = xin + ky*36;         // 16B-aligned (4*oxq)
            float xv[6];
            float4 a = *(const float4*)(xr);
            float2 c = *(const float2*)(xr + 4);
            xv[0]=a.x; xv[1]=a.y; xv[2]=a.z; xv[3]=a.w; xv[4]=c.x; xv[5]=c.y;
            const float* wp = g_w2t + ((cin*4+ky)*4)*64 + 4*cq;
            #pragma unroll
            for (int kx = 0; kx < 4; kx++) {
                float4 wv = *(const float4*)(wp + kx*64);
                float i0 = xv[kx], i1 = xv[kx+2];
                acc[0][0] += i0*wv.x; acc[0][1] += i0*wv.y;
                acc[0][2] += i0*wv.z; acc[0][3] += i0*wv.w;
                acc[1][0] += i1*wv.x; acc[1][1] += i1*wv.y;
                acc[1][2] += i1*wv.z; acc[1][3] += i1*wv.w;
            }
        }
    }
    if (!oy_ok) return;
    #pragma unroll
    for (int j = 0; j < 4; j++) {
        int co = cq*4 + j;
        float b = bias[co];
        #pragma unroll
        for (int i = 0; i < 2; i++) {
            int ox = 2*oxq + i;
            if (ox < 13) {
                float v = acc[i][j] + b;
                g_c2[((size_t)(n*64+co)*13 + oy)*13 + ox] = v > 0.f ? v : 0.f;
            }
        }
    }
}

// ---------------- conv3: (N,64,13,13) -> relu (N,64,6,6), k3 s2 ----------------
// grid(2048), block 288 (9 warps). Whole 43KB input staged in smem;
// thread: sq(18) x cq(16); tile 2 spatial x 4 cout. Inner reads are broadcast LDS.
__global__ void k_conv3(const float* __restrict__ bias) {
    __shared__ float xs[64*169];   // 10816 floats = 43.3 KB
    int n = blockIdx.x;
    int t = threadIdx.x;
    {
        const float4* src = (const float4*)(g_c2 + (size_t)n*10816);
        float4* dst = (float4*)xs;
        for (int i = t; i < 2704; i += 288) dst[i] = src[i];
    }
    __syncthreads();
    int sq = t % 18, cq = t / 18;    // cq 0..15
    int s0 = sq*2;                   // pair within one row (6 even)
    int sy = s0/6, sx = s0%6;
    float acc[2][4] = {};
    for (int cin = 0; cin < 64; cin++) {
        const float* xc = xs + cin*169;
        #pragma unroll
        for (int ky = 0; ky < 3; ky++) {
            const float* row = xc + (2*sy+ky)*13 + 2*sx;
            #pragma unroll
            for (int kx = 0; kx < 3; kx++) {
                float4 wv = *(const float4*)(g_w3t + ((cin*3+ky)*3+kx)*64 + 4*cq);
                float i0 = row[kx];
                float i1 = row[kx+2];
                acc[0][0] += i0*wv.x; acc[0][1] += i0*wv.y;
                acc[0][2] += i0*wv.z; acc[0][3] += i0*wv.w;
                acc[1][0] += i1*wv.x; acc[1][1] += i1*wv.y;
                acc[1][2] += i1*wv.z; acc[1][3] += i1*wv.w;
            }
        }
    }
    #pragma unroll
    for (int j = 0; j < 4; j++) {
        int co = cq*4 + j;
        float b = bias[co];
        #pragma unroll
        for (int i = 0; i < 2; i++) {
            float v = acc[i][j] + b;
            g_c3[(size_t)(n*64+co)*36 + s0 + i] = v > 0.f ? v : 0.f;
        }
    }
}

// ---------------- CBAM channel attention ----------------
__global__ void k_chatt(const float* __restrict__ fc1w, const float* __restrict__ fc2w) {
    __shared__ float pm[64], px[64], hsh[32];
    int n = blockIdx.x, c = threadIdx.x;
    const float* p = g_c3 + (size_t)(n*64+c)*36;
    float sum = 0.f, mx = -1e30f;
    #pragma unroll
    for (int s = 0; s < 36; s++) { float v = p[s]; sum += v; mx = fmaxf(mx, v); }
    pm[c] = sum * (1.f/36.f); px[c] = mx;
    __syncthreads();
    if (c < 32) {
        int k = c & 15;
        const float* src = (c < 16) ? pm : px;
        float a = 0.f;
        #pragma unroll
        for (int j = 0; j < 64; j++) a += fc1w[k*64+j]*src[j];
        hsh[c] = fmaxf(a, 0.f);
    }
    __syncthreads();
    float a = 0.f;
    #pragma unroll
    for (int k = 0; k < 16; k++) a += fc2w[c*16+k]*(hsh[k] + hsh[16+k]);
    g_catt[n*64+c] = 1.f/(1.f+expf(-a));
}

// ---------------- CBAM spatial attention + write tokens (N,36,64) ----------------
__global__ void k_spatial(const float* __restrict__ spw) {
    __shared__ float sh[2304], m2[36], x2[36], ss[36];
    int n = blockIdx.x, t = threadIdx.x;
    for (int o = t; o < 2304; o += 256)
        sh[o] = g_c3[(size_t)n*2304 + o] * g_catt[n*64 + o/36];
    __syncthreads();
    if (t < 36) {
        float sum = 0.f, mx = -1e30f;
        #pragma unroll
        for (int c = 0; c < 64; c++) { float v = sh[c*36+t]; sum += v; mx = fmaxf(mx, v); }
        m2[t] = sum*(1.f/64.f); x2[t] = mx;
    }
    __syncthreads();
    if (t < 36) {
        int sy = t/6, sx = t%6;
        float a = 0.f;
        for (int ky = 0; ky < 7; ky++) {
            int iy = sy + ky - 3; if (iy < 0 || iy >= 6) continue;
            for (int kx = 0; kx < 7; kx++) {
                int ix = sx + kx - 3; if (ix < 0 || ix >= 6) continue;
                a += spw[ky*7+kx]*m2[iy*6+ix] + spw[49+ky*7+kx]*x2[iy*6+ix];
            }
        }
        ss[t] = 1.f/(1.f+expf(-a));
    }
    __syncthreads();
    for (int o = t; o < 2304; o += 256) {
        int c = o/36, s = o%36;
        g_tok[((size_t)n*36 + s)*64 + c] = sh[o]*ss[s];
    }
}

// ---------------- generic SGEMM: C(M,N) = act(A(M,K) @ W(N,K)^T + bias) ----------------
template<int RELU, int BIAS>
__global__ void k_gemm(const float* __restrict__ A, const float* __restrict__ W,
                       const float* __restrict__ bias, float* __restrict__ C,
                       int M, int N, int K) {
    __shared__ float As[16][64], Ws[16][64];
    int m0 = blockIdx.x*64, n0 = blockIdx.y*64;
    int tid = threadIdx.x;
    int lr = tid >> 2, lk = (tid & 3) << 2;
    int tx = tid & 15, ty = tid >> 4;
    float acc[4][4] = {};
    for (int k0 = 0; k0 < K; k0 += 16) {
        float4 a = *(const float4*)(A + (size_t)(m0+lr)*K + k0 + lk);
        float4 w = *(const float4*)(W + (size_t)(n0+lr)*K + k0 + lk);
        As[lk  ][lr] = a.x; As[lk+1][lr] = a.y; As[lk+2][lr] = a.z; As[lk+3][lr] = a.w;
        Ws[lk  ][lr] = w.x; Ws[lk+1][lr] = w.y; Ws[lk+2][lr] = w.z; Ws[lk+3][lr] = w.w;
        __syncthreads();
        #pragma unroll
        for (int kk = 0; kk < 16; kk++) {
            float4 av = *(const float4*)&As[kk][tx<<2];
            float4 wv = *(const float4*)&Ws[kk][ty<<2];
            float ar[4] = {av.x, av.y, av.z, av.w};
            float wr[4] = {wv.x, wv.y, wv.z, wv.w};
            #pragma unroll
            for (int i = 0; i < 4; i++)
                #pragma unroll
                for (int j = 0; j < 4; j++)
                    acc[i][j] += ar[i]*wr[j];
        }
        __syncthreads();
    }
    #pragma unroll
    for (int i = 0; i < 4; i++) {
        int m = m0 + (tx<<2) + i;
        #pragma unroll
        for (int j = 0; j < 4; j++) {
            int nn = n0 + (ty<<2) + j;
            float v = acc[i][j];
            if (BIAS) v += bias[nn];
            if (RELU) v = fmaxf(v, 0.f);
            C[(size_t)m*N + nn] = v;
        }
    }
}

// ---------------- per-(n,head) attention over 36 tokens ----------------
__global__ void k_attn() {
    int head = blockIdx.x, n = blockIdx.y, t = threadIdx.x;
    __shared__ float qs[36*16], ks[36*16], vs[36*16];
    for (int idx = t; idx < 576; idx += 64) {
        int s = idx >> 4, d = idx & 15;
        const float* base = g_qkv + ((size_t)n*36 + s)*192 + head*16 + d;
        qs[idx] = base[0]; ks[idx] = base[64]; vs[idx] = base[128];
    }
    __syncthreads();
    if (t < 36) {
        float qr[16];
        #pragma unroll
        for (int d = 0; d < 16; d++) qr[d] = qs[t*16+d];
        float sc[36]; float mx = -1e30f;
        #pragma unroll
        for (int s2 = 0; s2 < 36; s2++) {
            float a = 0.f;
            #pragma unroll
            for (int d = 0; d < 16; d++) a += qr[d]*ks[s2*16+d];
            a *= 0.25f;
            sc[s2] = a; mx = fmaxf(mx, a);
        }
        float sum = 0.f;
        #pragma unroll
        for (int s2 = 0; s2 < 36; s2++) { float e = expf(sc[s2]-mx); sc[s2] = e; sum += e; }
        float inv = 1.f/sum;
        #pragma unroll
        for (int d = 0; d < 16; d++) {
            float o = 0.f;
            #pragma unroll
            for (int s2 = 0; s2 < 36; s2++) o += sc[s2]*vs[s2*16+d];
            g_attn[((size_t)n*36 + t)*64 + head*16 + d] = o*inv;
        }
    }
}

// ---------------- proj + residual, writes (N,64,36) layout for FC ----------------
__global__ void k_proj(const float* __restrict__ projw, const float* __restrict__ projb) {
    __shared__ float at[2304];
    int n = blockIdx.x, t = threadIdx.x;
    for (int o = t; o < 2304; o += 256) at[o] = g_attn[(size_t)n*2304 + o];
    __syncthreads();
    for (int o = t; o < 2304; o += 256) {
        int c = o/36, s = o%36;
        const float4* pw = (const float4*)(projw + c*64);
        const float4* av = (const float4*)(at + s*64);
        float a = 0.f;
        #pragma unroll
        for (int j = 0; j < 16; j++) {
            float4 p = pw[j], q = av[j];
            a += p.x*q.x + p.y*q.y + p.z*q.z + p.w*q.w;
        }
        g_h2[(size_t)n*2304 + o] = g_tok[((size_t)n*36 + s)*64 + c] + a + projb[c];
    }
}

// ---------------- masked GRU scan: 32 independent batch chains ----------------
__global__ void k_gru(const float* __restrict__ done, const float* __restrict__ h0,
                      const float* __restrict__ bhh) {
    int b = blockIdx.x, t = threadIdx.x;
    __shared__ float h_s[128], hm_s[128], gh_s[384];
    h_s[t] = h0[b*128 + t];
    __syncthreads();
    for (int step = 0; step < 64; step++) {
        float dt = done[step*32 + b];
        hm_s[t] = (1.f - dt)*h_s[t];
        __syncthreads();
        if (t < 96) {
            int g = t*4;
            float a0 = bhh[g], a1 = bhh[g+1], a2 = bhh[g+2], a3 = bhh[g+3];
            #pragma unroll 8
            for (int k = 0; k < 128; k++) {
                float hm = hm_s[k];
                float4 w = *(const float4*)(g_whht + k*384 + g);
                a0 += w.x*hm; a1 += w.y*hm; a2 += w.z*hm; a3 += w.w*hm;
            }
            gh_s[g] = a0; gh_s[g+1] = a1; gh_s[g+2] = a2; gh_s[g+3] = a3;
        }
        __syncthreads();
        int row = step*32 + b;
        float xr = g_gx[(size_t)row*384 + t];
        float xz = g_gx[(size_t)row*384 + 128 + t];
        float xn = g_gx[(size_t)row*384 + 256 + t];
        float hr = gh_s[t], hz = gh_s[128+t], hn = gh_s[256+t];
        float rg = 1.f/(1.f+expf(-(xr+hr)));
        float zg = 1.f/(1.f+expf(-(xz+hz)));
        float ng = tanhf(xn + rg*hn);
        float hnew = (1.f-zg)*ng + zg*hm_s[t];
        h_s[t] = hnew;
        g_hid[(size_t)row*128 + t] = hnew;
        __syncthreads();
    }
}

// ---------------- critic head: (2048,128) @ crw^T + crb ----------------
__global__ void k_critic(const float* __restrict__ crw, const float* __restrict__ crb,
                         float* __restrict__ out) {
    int warp = threadIdx.x >> 5, lane = threadIdx.x & 31;
    int row = blockIdx.x*8 + warp;
    const float4* h4 = (const float4*)(g_hid + (size_t)row*128);
    float4 hv = h4[lane];
    float4 wv = ((const float4*)crw)[lane];
    float s = hv.x*wv.x + hv.y*wv.y + hv.z*wv.z + hv.w*wv.w;
    #pragma unroll
    for (int o = 16; o; o >>= 1) s += __shfl_down_sync(0xffffffffu, s, o);
    if (lane == 0) out[row] = s + crb[0];
}

// ---------------- launch ----------------
extern "C" void kernel_launch(void* const* d_in, const int* in_sizes, int n_in,
                              void* d_out, int out_size) {
    const float* x    = (const float*)d_in[0];
    const float* done = (const float*)d_in[1];
    const float* gru0 = (const float*)d_in[2];
    const float* c1w  = (const float*)d_in[3];
    const float* c1b  = (const float*)d_in[4];
    const float* c2w  = (const float*)d_in[5];
    const float* c2b  = (const float*)d_in[6];
    const float* c3w  = (const float*)d_in[7];
    const float* c3b  = (const float*)d_in[8];
    const float* fc1w = (const float*)d_in[9];
    const float* fc2w = (const float*)d_in[10];
    const float* spw  = (const float*)d_in[11];
    const float* qkvw = (const float*)d_in[12];
    const float* projw= (const float*)d_in[13];
    const float* projb= (const float*)d_in[14];
    const float* fcw  = (const float*)d_in[15];
    const float* fcb  = (const float*)d_in[16];
    const float* wih  = (const float*)d_in[17];
    const float* whh  = (const float*)d_in[18];
    const float* bih  = (const float*)d_in[19];
    const float* bhh  = (const float*)d_in[20];
    const float* crw  = (const float*)d_in[21];
    const float* crb  = (const float*)d_in[22];
    float* out = (float*)d_out;

    float *p_tok, *p_qkv, *p_h2, *p_feat, *p_gx;
    cudaGetSymbolAddress((void**)&p_tok,  g_tok);
    cudaGetSymbolAddress((void**)&p_qkv,  g_qkv);
    cudaGetSymbolAddress((void**)&p_h2,   g_h2);
    cudaGetSymbolAddress((void**)&p_feat, g_feat);
    cudaGetSymbolAddress((void**)&p_gx,   g_gx);

    // prep (ordered so the ncu sampled launch lands on k_conv1)
    k_transpose<<<(32*256 + 255)/256, 256>>>(c1w, 32, 256, 0);
    k_transpose<<<(64*512 + 255)/256, 256>>>(c2w, 64, 512, 1);
    k_transpose<<<(384*128 + 255)/256, 256>>>(whh, 384, 128, 3);

    // conv backbone
    k_conv1<<<dim3(14, 2048), 224>>>(x, c1b);
    k_transpose<<<(64*576 + 255)/256, 256>>>(c3w, 64, 576, 2);
    k_conv2<<<dim3(7, 2048), 224>>>(c2b);
    k_conv3<<<2048, 288>>>(c3b);

    // CBAM
    k_chatt<<<2048, 64>>>(fc1w, fc2w);
    k_spatial<<<2048, 256>>>(spw);

    // spatial self-attention
    k_gemm<0,0><<<dim3(73728/64, 192/64), 256>>>(p_tok, qkvw, (const float*)0, p_qkv, 73728, 192, 64);
    k_attn<<<dim3(4, 2048), 64>>>();
    k_proj<<<2048, 256>>>(projw, projb);

    // FC + GRU input gates
    k_gemm<1,1><<<dim3(2048/64, 256/64), 256>>>(p_h2, fcw, fcb, p_feat, 2048, 256, 2304);
    k_gemm<0,1><<<dim3(2048/64, 384/64), 256>>>(p_feat, wih, bih, p_gx, 2048, 384, 256);

    // GRU scan + critic
    k_gru<<<32, 128>>>(done, gru0, bhh);
    k_critic<<<2048/8, 256>>>(crw, crb, out);
}

// round 5
// speedup vs baseline: 1.2195x; 1.2195x over previous
#include <cuda_runtime.h>
#include <math.h>

// ---------------- scratch (device globals; no mallocs) ----------------
// g_c1 rows padded 28 -> 36 floats so conv2 can do unconditional vector loads.
__device__ float g_c1[2048*32*28*36];   // conv1 out (padded rows)
__device__ float g_c2[2048*64*13*13];   // conv2 out
__device__ float g_c3[2048*64*36];      // conv3 out (N,64,36)
__device__ float g_catt[2048*64];       // channel attention
__device__ float g_tok[2048*36*64];     // tokens (N,36,64) post-CBAM
__device__ float g_qkv[2048*36*192];    // qkv
__device__ float g_attn[2048*36*64];    // attention out (N,36,64)
__device__ float g_h2[2048*2304];       // residual, (N,64,36) flat -> FC input
__device__ float g_feat[2048*256];      // FC out
__device__ float g_gx[2048*384];        // input-side GRU gates
__device__ float g_hid[2048*128];       // GRU hidden per step
__device__ float g_w1t[256*32];         // conv weights transposed: [k][cout]
__device__ float g_w2t[512*64];
__device__ float g_w3t[576*64];
__device__ float g_whht[128*384];       // whh transposed [k][gate]

// ---------------- weight transpose prep ----------------
__global__ void k_transpose(const float* __restrict__ w, int Cout, int K, int which) {
    int idx = blockIdx.x*256 + threadIdx.x;
    if (idx >= Cout*K) return;
    int co = idx / K, k = idx % K;
    float* dst = (which==0) ? g_w1t : (which==1) ? g_w2t : (which==2) ? g_w3t : g_whht;
    dst[k*Cout + co] = w[idx];
}

// ---------------- conv1: (N,4,116,116) -> relu (N,32,28,28pad36), k8 s4 --------
// grid(7, 2048), block 224 (7 warps, 4 oy rows per block).
// thread: cq(8, fastest) x oxq(7); tile 4 ox x 4 cout. Weights staged in smem.
// Per (cin,ky): 128 FFMA (64 issue-cyc) vs 8 LDS.128 (32 crossbar-cyc) + 5 LDG.128
// -> fma-bound with ~35% L1TEX headroom.
__global__ void __launch_bounds__(224) k_conv1(const float* __restrict__ x,
                                               const float* __restrict__ bias) {
    __shared__ float ws[256*32];     // 32 KB, [k][cout] layout
    for (int i = threadIdx.x; i < 2048; i += 224)
        ((float4*)ws)[i] = ((const float4*)g_w1t)[i];
    __syncthreads();
    int n  = blockIdx.y;
    int oy = blockIdx.x*4 + threadIdx.x/56;
    int t  = threadIdx.x % 56;
    int cq  = t % 8;            // cout quad, fastest for broadcast-friendly LDS
    int oxq = t / 8;            // 0..6 -> ox0 = 4*oxq
    float acc[4][4] = {};
    for (int cin = 0; cin < 4; cin++) {
        const float* xin = x + (size_t)(n*4+cin)*13456 + 4*oy*116 + 16*oxq;
        #pragma unroll
        for (int ky = 0; ky < 8; ky++) {
            const float* xr = xin + ky*116;        // 64B-aligned (16*oxq)
            float xv[20];
            #pragma unroll
            for (int u = 0; u < 5; u++) {
                float4 v = *(const float4*)(xr + 4*u);
                xv[4*u]=v.x; xv[4*u+1]=v.y; xv[4*u+2]=v.z; xv[4*u+3]=v.w;
            }
            const float* wp = ws + ((cin*8+ky)*8)*32 + 4*cq;
            #pragma unroll
            for (int kx = 0; kx < 8; kx++) {
                float4 wv = *(const float4*)(wp + kx*32);
                #pragma unroll
                for (int i = 0; i < 4; i++) {
                    float iv = xv[4*i+kx];
                    acc[i][0] += iv*wv.x; acc[i][1] += iv*wv.y;
                    acc[i][2] += iv*wv.z; acc[i][3] += iv*wv.w;
                }
            }
        }
    }
    #pragma unroll
    for (int j = 0; j < 4; j++) {
        int co = cq*4 + j;
        float b = bias[co];
        #pragma unroll
        for (int i = 0; i < 4; i++) {
            float v = acc[i][j] + b;
            g_c1[((size_t)(n*32+co)*28 + oy)*36 + 4*oxq + i] = v > 0.f ? v : 0.f;
        }
    }
}

// ---------------- conv2: (N,32,28pad36) -> relu (N,64,13,13), k4 s2 ------------
// grid(7, 2048), block 128 (4 warps, 2 oy per block; oy==13 retires early —
// legal, no barriers below). thread: oxq(4) x cq(16); tile 4 ox x 4 cout.
// Per (cin,ky): 64 FFMA vs 4 weight LDG.128 (128B distinct/warp, L1-hot) + 2.5
// input vector loads -> fma-bound.
__global__ void __launch_bounds__(128) k_conv2(const float* __restrict__ bias) {
    int n = blockIdx.y;
    int oy = blockIdx.x*2 + threadIdx.x/64;
    if (oy >= 13) return;                     // no __syncthreads below: safe
    int t = threadIdx.x % 64;
    int oxq = t % 4, cq = t / 4;  // cq 0..15
    float acc[4][4] = {};
    for (int cin = 0; cin < 32; cin++) {
        const float* xin = g_c1 + (size_t)(n*32+cin)*1008 + 2*oy*36 + 8*oxq;
        #pragma unroll
        for (int ky = 0; ky < 4; ky++) {
            const float* xr = xin + ky*36;         // 32B-aligned (8*oxq)
            float xv[10];
            float4 a = *(const float4*)(xr);
            float4 b = *(const float4*)(xr + 4);
            float2 c = *(const float2*)(xr + 8);
            xv[0]=a.x; xv[1]=a.y; xv[2]=a.z; xv[3]=a.w;
            xv[4]=b.x; xv[5]=b.y; xv[6]=b.z; xv[7]=b.w;
            xv[8]=c.x; xv[9]=c.y;
            const float* wp = g_w2t + ((cin*4+ky)*4)*64 + 4*cq;
            #pragma unroll
            for (int kx = 0; kx < 4; kx++) {
                float4 wv = *(const float4*)(wp + kx*64);
                #pragma unroll
                for (int i = 0; i < 4; i++) {
                    float iv = xv[2*i+kx];
                    acc[i][0] += iv*wv.x; acc[i][1] += iv*wv.y;
                    acc[i][2] += iv*wv.z; acc[i][3] += iv*wv.w;
                }
            }
        }
    }
    #pragma unroll
    for (int j = 0; j < 4; j++) {
        int co = cq*4 + j;
        float b = bias[co];
        #pragma unroll
        for (int i = 0; i < 4; i++) {
            int ox = 4*oxq + i;
            if (ox < 13) {
                float v = acc[i][j] + b;
                g_c2[((size_t)(n*64+co)*13 + oy)*13 + ox] = v > 0.f ? v : 0.f;
            }
        }
    }
}

// ---------------- conv3: (N,64,13,13) -> relu (N,64,6,6), k3 s2 ----------------
// grid(2048), block 288 (9 warps). Whole 43KB input staged in smem;
// thread: sq(18) x cq(16); tile 2 spatial x 4 cout. Inner reads are broadcast LDS.
__global__ void k_conv3(const float* __restrict__ bias) {
    __shared__ float xs[64*169];   // 10816 floats = 43.3 KB
    int n = blockIdx.x;
    int t = threadIdx.x;
    {
        const float4* src = (const float4*)(g_c2 + (size_t)n*10816);
        float4* dst = (float4*)xs;
        for (int i = t; i < 2704; i += 288) dst[i] = src[i];
    }
    __syncthreads();
    int sq = t % 18, cq = t / 18;    // cq 0..15
    int s0 = sq*2;                   // pair within one row (6 even)
    int sy = s0/6, sx = s0%6;
    float acc[2][4] = {};
    for (int cin = 0; cin < 64; cin++) {
        const float* xc = xs + cin*169;
        #pragma unroll
        for (int ky = 0; ky < 3; ky++) {
            const float* row = xc + (2*sy+ky)*13 + 2*sx;
            #pragma unroll
            for (int kx = 0; kx < 3; kx++) {
                float4 wv = *(const float4*)(g_w3t + ((cin*3+ky)*3+kx)*64 + 4*cq);
                float i0 = row[kx];
                float i1 = row[kx+2];
                acc[0][0] += i0*wv.x; acc[0][1] += i0*wv.y;
                acc[0][2] += i0*wv.z; acc[0][3] += i0*wv.w;
                acc[1][0] += i1*wv.x; acc[1][1] += i1*wv.y;
                acc[1][2] += i1*wv.z; acc[1][3] += i1*wv.w;
            }
        }
    }
    #pragma unroll
    for (int j = 0; j < 4; j++) {
        int co = cq*4 + j;
        float b = bias[co];
        #pragma unroll
        for (int i = 0; i < 2; i++) {
            float v = acc[i][j] + b;
            g_c3[(size_t)(n*64+co)*36 + s0 + i] = v > 0.f ? v : 0.f;
        }
    }
}

// ---------------- CBAM channel attention ----------------
__global__ void k_chatt(const float* __restrict__ fc1w, const float* __restrict__ fc2w) {
    __shared__ float pm[64], px[64], hsh[32];
    int n = blockIdx.x, c = threadIdx.x;
    const float* p = g_c3 + (size_t)(n*64+c)*36;
    float sum = 0.f, mx = -1e30f;
    #pragma unroll
    for (int s = 0; s < 36; s++) { float v = p[s]; sum += v; mx = fmaxf(mx, v); }
    pm[c] = sum * (1.f/36.f); px[c] = mx;
    __syncthreads();
    if (c < 32) {
        int k = c & 15;
        const float* src = (c < 16) ? pm : px;
        float a = 0.f;
        #pragma unroll
        for (int j = 0; j < 64; j++) a += fc1w[k*64+j]*src[j];
        hsh[c] = fmaxf(a, 0.f);
    }
    __syncthreads();
    float a = 0.f;
    #pragma unroll
    for (int k = 0; k < 16; k++) a += fc2w[c*16+k]*(hsh[k] + hsh[16+k]);
    g_catt[n*64+c] = 1.f/(1.f+expf(-a));
}

// ---------------- CBAM spatial attention + write tokens (N,36,64) ----------------
__global__ void k_spatial(const float* __restrict__ spw) {
    __shared__ float sh[2304], m2[36], x2[36], ss[36];
    int n = blockIdx.x, t = threadIdx.x;
    for (int o = t; o < 2304; o += 256)
        sh[o] = g_c3[(size_t)n*2304 + o] * g_catt[n*64 + o/36];
    __syncthreads();
    if (t < 36) {
        float sum = 0.f, mx = -1e30f;
        #pragma unroll
        for (int c = 0; c < 64; c++) { float v = sh[c*36+t]; sum += v; mx = fmaxf(mx, v); }
        m2[t] = sum*(1.f/64.f); x2[t] = mx;
    }
    __syncthreads();
    if (t < 36) {
        int sy = t/6, sx = t%6;
        float a = 0.f;
        for (int ky = 0; ky < 7; ky++) {
            int iy = sy + ky - 3; if (iy < 0 || iy >= 6) continue;
            for (int kx = 0; kx < 7; kx++) {
                int ix = sx + kx - 3; if (ix < 0 || ix >= 6) continue;
                a += spw[ky*7+kx]*m2[iy*6+ix] + spw[49+ky*7+kx]*x2[iy*6+ix];
            }
        }
        ss[t] = 1.f/(1.f+expf(-a));
    }
    __syncthreads();
    for (int o = t; o < 2304; o += 256) {
        int c = o/36, s = o%36;
        g_tok[((size_t)n*36 + s)*64 + c] = sh[o]*ss[s];
    }
}

// ---------------- generic SGEMM: C(M,N) = act(A(M,K) @ W(N,K)^T + bias) ----------------
template<int RELU, int BIAS>
__global__ void k_gemm(const float* __restrict__ A, const float* __restrict__ W,
                       const float* __restrict__ bias, float* __restrict__ C,
                       int M, int N, int K) {
    __shared__ float As[16][64], Ws[16][64];
    int m0 = blockIdx.x*64, n0 = blockIdx.y*64;
    int tid = threadIdx.x;
    int lr = tid >> 2, lk = (tid & 3) << 2;
    int tx = tid & 15, ty = tid >> 4;
    float acc[4][4] = {};
    for (int k0 = 0; k0 < K; k0 += 16) {
        float4 a = *(const float4*)(A + (size_t)(m0+lr)*K + k0 + lk);
        float4 w = *(const float4*)(W + (size_t)(n0+lr)*K + k0 + lk);
        As[lk  ][lr] = a.x; As[lk+1][lr] = a.y; As[lk+2][lr] = a.z; As[lk+3][lr] = a.w;
        Ws[lk  ][lr] = w.x; Ws[lk+1][lr] = w.y; Ws[lk+2][lr] = w.z; Ws[lk+3][lr] = w.w;
        __syncthreads();
        #pragma unroll
        for (int kk = 0; kk < 16; kk++) {
            float4 av = *(const float4*)&As[kk][tx<<2];
            float4 wv = *(const float4*)&Ws[kk][ty<<2];
            float ar[4] = {av.x, av.y, av.z, av.w};
            float wr[4] = {wv.x, wv.y, wv.z, wv.w};
            #pragma unroll
            for (int i = 0; i < 4; i++)
                #pragma unroll
                for (int j = 0; j < 4; j++)
                    acc[i][j] += ar[i]*wr[j];
        }
        __syncthreads();
    }
    #pragma unroll
    for (int i = 0; i < 4; i++) {
        int m = m0 + (tx<<2) + i;
        #pragma unroll
        for (int j = 0; j < 4; j++) {
            int nn = n0 + (ty<<2) + j;
            float v = acc[i][j];
            if (BIAS) v += bias[nn];
            if (RELU) v = fmaxf(v, 0.f);
            C[(size_t)m*N + nn] = v;
        }
    }
}

// ---------------- per-(n,head) attention over 36 tokens ----------------
__global__ void k_attn() {
    int head = blockIdx.x, n = blockIdx.y, t = threadIdx.x;
    __shared__ float qs[36*16], ks[36*16], vs[36*16];
    for (int idx = t; idx < 576; idx += 64) {
        int s = idx >> 4, d = idx & 15;
        const float* base = g_qkv + ((size_t)n*36 + s)*192 + head*16 + d;
        qs[idx] = base[0]; ks[idx] = base[64]; vs[idx] = base[128];
    }
    __syncthreads();
    if (t < 36) {
        float qr[16];
        #pragma unroll
        for (int d = 0; d < 16; d++) qr[d] = qs[t*16+d];
        float sc[36]; float mx = -1e30f;
        #pragma unroll
        for (int s2 = 0; s2 < 36; s2++) {
            float a = 0.f;
            #pragma unroll
            for (int d = 0; d < 16; d++) a += qr[d]*ks[s2*16+d];
            a *= 0.25f;
            sc[s2] = a; mx = fmaxf(mx, a);
        }
        float sum = 0.f;
        #pragma unroll
        for (int s2 = 0; s2 < 36; s2++) { float e = expf(sc[s2]-mx); sc[s2] = e; sum += e; }
        float inv = 1.f/sum;
        #pragma unroll
        for (int d = 0; d < 16; d++) {
            float o = 0.f;
            #pragma unroll
            for (int s2 = 0; s2 < 36; s2++) o += sc[s2]*vs[s2*16+d];
            g_attn[((size_t)n*36 + t)*64 + head*16 + d] = o*inv;
        }
    }
}

// ---------------- proj + residual, writes (N,64,36) layout for FC ----------------
__global__ void k_proj(const float* __restrict__ projw, const float* __restrict__ projb) {
    __shared__ float at[2304];
    int n = blockIdx.x, t = threadIdx.x;
    for (int o = t; o < 2304; o += 256) at[o] = g_attn[(size_t)n*2304 + o];
    __syncthreads();
    for (int o = t; o < 2304; o += 256) {
        int c = o/36, s = o%36;
        const float4* pw = (const float4*)(projw + c*64);
        const float4* av = (const float4*)(at + s*64);
        float a = 0.f;
        #pragma unroll
        for (int j = 0; j < 16; j++) {
            float4 p = pw[j], q = av[j];
            a += p.x*q.x + p.y*q.y + p.z*q.z + p.w*q.w;
        }
        g_h2[(size_t)n*2304 + o] = g_tok[((size_t)n*36 + s)*64 + c] + a + projb[c];
    }
}

// ---------------- masked GRU scan: 32 independent batch chains ----------------
__global__ void k_gru(const float* __restrict__ done, const float* __restrict__ h0,
                      const float* __restrict__ bhh) {
    int b = blockIdx.x, t = threadIdx.x;
    __shared__ float h_s[128], hm_s[128], gh_s[384];
    h_s[t] = h0[b*128 + t];
    __syncthreads();
    for (int step = 0; step < 64; step++) {
        float dt = done[step*32 + b];
        hm_s[t] = (1.f - dt)*h_s[t];
        __syncthreads();
        if (t < 96) {
            int g = t*4;
            float a0 = bhh[g], a1 = bhh[g+1], a2 = bhh[g+2], a3 = bhh[g+3];
            #pragma unroll 8
            for (int k = 0; k < 128; k++) {
                float hm = hm_s[k];
                float4 w = *(const float4*)(g_whht + k*384 + g);
                a0 += w.x*hm; a1 += w.y*hm; a2 += w.z*hm; a3 += w.w*hm;
            }
            gh_s[g] = a0; gh_s[g+1] = a1; gh_s[g+2] = a2; gh_s[g+3] = a3;
        }
        __syncthreads();
        int row = step*32 + b;
        float xr = g_gx[(size_t)row*384 + t];
        float xz = g_gx[(size_t)row*384 + 128 + t];
        float xn = g_gx[(size_t)row*384 + 256 + t];
        float hr = gh_s[t], hz = gh_s[128+t], hn = gh_s[256+t];
        float rg = 1.f/(1.f+expf(-(xr+hr)));
        float zg = 1.f/(1.f+expf(-(xz+hz)));
        float ng = tanhf(xn + rg*hn);
        float hnew = (1.f-zg)*ng + zg*hm_s[t];
        h_s[t] = hnew;
        g_hid[(size_t)row*128 + t] = hnew;
        __syncthreads();
    }
}

// ---------------- critic head: (2048,128) @ crw^T + crb ----------------
__global__ void k_critic(const float* __restrict__ crw, const float* __restrict__ crb,
                         float* __restrict__ out) {
    int warp = threadIdx.x >> 5, lane = threadIdx.x & 31;
    int row = blockIdx.x*8 + warp;
    const float4* h4 = (const float4*)(g_hid + (size_t)row*128);
    float4 hv = h4[lane];
    float4 wv = ((const float4*)crw)[lane];
    float s = hv.x*wv.x + hv.y*wv.y + hv.z*wv.z + hv.w*wv.w;
    #pragma unroll
    for (int o = 16; o; o >>= 1) s += __shfl_down_sync(0xffffffffu, s, o);
    if (lane == 0) out[row] = s + crb[0];
}

// ---------------- launch ----------------
extern "C" void kernel_launch(void* const* d_in, const int* in_sizes, int n_in,
                              void* d_out, int out_size) {
    const float* x    = (const float*)d_in[0];
    const float* done = (const float*)d_in[1];
    const float* gru0 = (const float*)d_in[2];
    const float* c1w  = (const float*)d_in[3];
    const float* c1b  = (const float*)d_in[4];
    const float* c2w  = (const float*)d_in[5];
    const float* c2b  = (const float*)d_in[6];
    const float* c3w  = (const float*)d_in[7];
    const float* c3b  = (const float*)d_in[8];
    const float* fc1w = (const float*)d_in[9];
    const float* fc2w = (const float*)d_in[10];
    const float* spw  = (const float*)d_in[11];
    const float* qkvw = (const float*)d_in[12];
    const float* projw= (const float*)d_in[13];
    const float* projb= (const float*)d_in[14];
    const float* fcw  = (const float*)d_in[15];
    const float* fcb  = (const float*)d_in[16];
    const float* wih  = (const float*)d_in[17];
    const float* whh  = (const float*)d_in[18];
    const float* bih  = (const float*)d_in[19];
    const float* bhh  = (const float*)d_in[20];
    const float* crw  = (const float*)d_in[21];
    const float* crb  = (const float*)d_in[22];
    float* out = (float*)d_out;

    float *p_tok, *p_qkv, *p_h2, *p_feat, *p_gx;
    cudaGetSymbolAddress((void**)&p_tok,  g_tok);
    cudaGetSymbolAddress((void**)&p_qkv,  g_qkv);
    cudaGetSymbolAddress((void**)&p_h2,   g_h2);
    cudaGetSymbolAddress((void**)&p_feat, g_feat);
    cudaGetSymbolAddress((void**)&p_gx,   g_gx);

    // prep (ordered so the ncu sampled launch lands on k_conv1)
    k_transpose<<<(32*256 + 255)/256, 256>>>(c1w, 32, 256, 0);
    k_transpose<<<(64*512 + 255)/256, 256>>>(c2w, 64, 512, 1);
    k_transpose<<<(384*128 + 255)/256, 256>>>(whh, 384, 128, 3);

    // conv backbone
    k_conv1<<<dim3(7, 2048), 224>>>(x, c1b);
    k_transpose<<<(64*576 + 255)/256, 256>>>(c3w, 64, 576, 2);
    k_conv2<<<dim3(7, 2048), 128>>>(c2b);
    k_conv3<<<2048, 288>>>(c3b);

    // CBAM
    k_chatt<<<2048, 64>>>(fc1w, fc2w);
    k_spatial<<<2048, 256>>>(spw);

    // spatial self-attention
    k_gemm<0,0><<<dim3(73728/64, 192/64), 256>>>(p_tok, qkvw, (const float*)0, p_qkv, 73728, 192, 64);
    k_attn<<<dim3(4, 2048), 64>>>();
    k_proj<<<2048, 256>>>(projw, projb);

    // FC + GRU input gates
    k_gemm<1,1><<<dim3(2048/64, 256/64), 256>>>(p_h2, fcw, fcb, p_feat, 2048, 256, 2304);
    k_gemm<0,1><<<dim3(2048/64, 384/64), 256>>>(p_feat, wih, bih, p_gx, 2048, 384, 256);

    // GRU scan + critic
    k_gru<<<32, 128>>>(done, gru0, bhh);
    k_critic<<<2048/8, 256>>>(crw, crb, out);
}

// round 6
// speedup vs baseline: 1.3000x; 1.0660x over previous
#include <cuda_runtime.h>
#include <math.h>

// ---------------- scratch (device globals; no mallocs) ----------------
// g_c1 rows padded 28 -> 36 floats so conv2 can do unconditional vector loads.
__device__ float g_c1[2048*32*28*36];   // conv1 out (padded rows)
__device__ float g_c2[2048*64*13*13];   // conv2 out
__device__ float g_c3[2048*64*36];      // conv3 out (N,64,36)
__device__ float g_catt[2048*64];       // channel attention
__device__ float g_tok[2048*36*64];     // tokens (N,36,64) post-CBAM
__device__ float g_qkv[2048*36*192];    // qkv
__device__ float g_attn[2048*36*64];    // attention out (N,36,64)
__device__ float g_h2[2048*2304];       // residual, (N,64,36) flat -> FC input
__device__ float g_feat[2048*256];      // FC out
__device__ float g_gx[2048*384];        // input-side GRU gates
__device__ float g_hid[2048*128];       // GRU hidden per step
__device__ float g_w1t[256*32];         // conv weights transposed: [k][cout]
__device__ float g_w2t[512*64];
__device__ float g_w3t[576*64];
__device__ float g_whht[128*384];       // whh transposed [k][gate]

// ---------------- weight transpose prep ----------------
__global__ void k_transpose(const float* __restrict__ w, int Cout, int K, int which) {
    int idx = blockIdx.x*256 + threadIdx.x;
    if (idx >= Cout*K) return;
    int co = idx / K, k = idx % K;
    float* dst = (which==0) ? g_w1t : (which==1) ? g_w2t : (which==2) ? g_w3t : g_whht;
    dst[k*Cout + co] = w[idx];
}

// ---------------- conv1: (N,4,116,116) -> relu (N,32,28,28pad36), k8 s4 --------
// grid(7, 2048), block 128 (4 warps = 4 oy rows). Warp = cq(8) x oxq(4);
// thread tile: 7 ox x 4 cout. Per (cin,ky): 224 FFMA vs 8 LDS.128 + 8 LDG.128.
__global__ void __launch_bounds__(128) k_conv1(const float* __restrict__ x,
                                               const float* __restrict__ bias) {
    __shared__ float ws[256*32];     // 32 KB, [k][cout] layout
    for (int i = threadIdx.x; i < 2048; i += 128)
        ((float4*)ws)[i] = ((const float4*)g_w1t)[i];
    __syncthreads();
    int n    = blockIdx.y;
    int oy   = blockIdx.x*4 + threadIdx.x/32;
    int lane = threadIdx.x % 32;
    int cq   = lane % 8;        // cout quad (broadcast-friendly LDS)
    int oxq  = lane / 8;        // 0..3 -> ox0 = 7*oxq
    float acc[7][4] = {};
    for (int cin = 0; cin < 4; cin++) {
        const float* xin = x + (size_t)(n*4+cin)*13456 + 4*oy*116 + 28*oxq;
        #pragma unroll
        for (int ky = 0; ky < 8; ky++) {
            const float* xr = xin + ky*116;        // 16B-aligned (112B*oxq etc.)
            float xv[32];
            #pragma unroll
            for (int u = 0; u < 8; u++) {
                float4 v = *(const float4*)(xr + 4*u);
                xv[4*u]=v.x; xv[4*u+1]=v.y; xv[4*u+2]=v.z; xv[4*u+3]=v.w;
            }
            const float* wp = ws + ((cin*8+ky)*8)*32 + 4*cq;
            #pragma unroll
            for (int kx = 0; kx < 8; kx++) {
                float4 wv = *(const float4*)(wp + kx*32);
                #pragma unroll
                for (int i = 0; i < 7; i++) {
                    float iv = xv[4*i+kx];
                    acc[i][0] += iv*wv.x; acc[i][1] += iv*wv.y;
                    acc[i][2] += iv*wv.z; acc[i][3] += iv*wv.w;
                }
            }
        }
    }
    #pragma unroll
    for (int j = 0; j < 4; j++) {
        int co = cq*4 + j;
        float b = bias[co];
        #pragma unroll
        for (int i = 0; i < 7; i++) {
            float v = acc[i][j] + b;
            g_c1[((size_t)(n*32+co)*28 + oy)*36 + 7*oxq + i] = v > 0.f ? v : 0.f;
        }
    }
}

// ---------------- conv2: (N,32,28pad36) -> relu (N,64,13,13), k4 s2 ------------
// grid(4, 2048), block 128 (4 warps = 4 oy rows; oy>=13 retires early — legal,
// no barriers). Warp = cq(16) x oxq(2); thread tile: 7 ox x 4 cout (ox=13 cut).
// Per (cin,ky): 112 FFMA vs 4 weight LDG.128 (L1-hot) + 8 input LD.64.
__global__ void __launch_bounds__(128) k_conv2(const float* __restrict__ bias) {
    int n = blockIdx.y;
    int oy = blockIdx.x*4 + threadIdx.x/32;
    if (oy >= 13) return;                     // no __syncthreads below: safe
    int lane = threadIdx.x % 32;
    int cq  = lane % 16;        // 0..15 -> cout quad
    int oxq = lane / 16;        // 0..1 -> ox0 = 7*oxq
    float acc[7][4] = {};
    for (int cin = 0; cin < 32; cin++) {
        const float* xin = g_c1 + (size_t)(n*32+cin)*1008 + 2*oy*36 + 14*oxq;
        #pragma unroll
        for (int ky = 0; ky < 4; ky++) {
            const float* xr = xin + ky*36;         // 8B-aligned (56B*oxq)
            float xv[16];
            #pragma unroll
            for (int u = 0; u < 8; u++) {
                float2 v = *(const float2*)(xr + 2*u);
                xv[2*u]=v.x; xv[2*u+1]=v.y;
            }
            const float* wp = g_w2t + ((cin*4+ky)*4)*64 + 4*cq;
            #pragma unroll
            for (int kx = 0; kx < 4; kx++) {
                float4 wv = *(const float4*)(wp + kx*64);
                #pragma unroll
                for (int i = 0; i < 7; i++) {
                    float iv = xv[2*i+kx];
                    acc[i][0] += iv*wv.x; acc[i][1] += iv*wv.y;
                    acc[i][2] += iv*wv.z; acc[i][3] += iv*wv.w;
                }
            }
        }
    }
    #pragma unroll
    for (int j = 0; j < 4; j++) {
        int co = cq*4 + j;
        float b = bias[co];
        #pragma unroll
        for (int i = 0; i < 7; i++) {
            int ox = 7*oxq + i;
            if (ox < 13) {
                float v = acc[i][j] + b;
                g_c2[((size_t)(n*64+co)*13 + oy)*13 + ox] = v > 0.f ? v : 0.f;
            }
        }
    }
}

// ---------------- conv3: (N,64,13,13) -> relu (N,64,6,6), k3 s2 ----------------
// grid(2048), block 288 (9 warps). Whole 43KB input staged in smem;
// thread: sq(18) x cq(16); tile 2 spatial x 4 cout. Inner reads are broadcast LDS.
__global__ void k_conv3(const float* __restrict__ bias) {
    __shared__ float xs[64*169];   // 10816 floats = 43.3 KB
    int n = blockIdx.x;
    int t = threadIdx.x;
    {
        const float4* src = (const float4*)(g_c2 + (size_t)n*10816);
        float4* dst = (float4*)xs;
        for (int i = t; i < 2704; i += 288) dst[i] = src[i];
    }
    __syncthreads();
    int sq = t % 18, cq = t / 18;    // cq 0..15
    int s0 = sq*2;                   // pair within one row (6 even)
    int sy = s0/6, sx = s0%6;
    float acc[2][4] = {};
    for (int cin = 0; cin < 64; cin++) {
        const float* xc = xs + cin*169;
        #pragma unroll
        for (int ky = 0; ky < 3; ky++) {
            const float* row = xc + (2*sy+ky)*13 + 2*sx;
            #pragma unroll
            for (int kx = 0; kx < 3; kx++) {
                float4 wv = *(const float4*)(g_w3t + ((cin*3+ky)*3+kx)*64 + 4*cq);
                float i0 = row[kx];
                float i1 = row[kx+2];
                acc[0][0] += i0*wv.x; acc[0][1] += i0*wv.y;
                acc[0][2] += i0*wv.z; acc[0][3] += i0*wv.w;
                acc[1][0] += i1*wv.x; acc[1][1] += i1*wv.y;
                acc[1][2] += i1*wv.z; acc[1][3] += i1*wv.w;
            }
        }
    }
    #pragma unroll
    for (int j = 0; j < 4; j++) {
        int co = cq*4 + j;
        float b = bias[co];
        #pragma unroll
        for (int i = 0; i < 2; i++) {
            float v = acc[i][j] + b;
            g_c3[(size_t)(n*64+co)*36 + s0 + i] = v > 0.f ? v : 0.f;
        }
    }
}

// ---------------- CBAM channel attention ----------------
__global__ void k_chatt(const float* __restrict__ fc1w, const float* __restrict__ fc2w) {
    __shared__ float pm[64], px[64], hsh[32];
    int n = blockIdx.x, c = threadIdx.x;
    const float* p = g_c3 + (size_t)(n*64+c)*36;
    float sum = 0.f, mx = -1e30f;
    #pragma unroll
    for (int s = 0; s < 36; s++) { float v = p[s]; sum += v; mx = fmaxf(mx, v); }
    pm[c] = sum * (1.f/36.f); px[c] = mx;
    __syncthreads();
    if (c < 32) {
        int k = c & 15;
        const float* src = (c < 16) ? pm : px;
        float a = 0.f;
        #pragma unroll
        for (int j = 0; j < 64; j++) a += fc1w[k*64+j]*src[j];
        hsh[c] = fmaxf(a, 0.f);
    }
    __syncthreads();
    float a = 0.f;
    #pragma unroll
    for (int k = 0; k < 16; k++) a += fc2w[c*16+k]*(hsh[k] + hsh[16+k]);
    g_catt[n*64+c] = 1.f/(1.f+expf(-a));
}

// ---------------- CBAM spatial attention + write tokens (N,36,64) ----------------
__global__ void k_spatial(const float* __restrict__ spw) {
    __shared__ float sh[2304], m2[36], x2[36], ss[36];
    int n = blockIdx.x, t = threadIdx.x;
    for (int o = t; o < 2304; o += 256)
        sh[o] = g_c3[(size_t)n*2304 + o] * g_catt[n*64 + o/36];
    __syncthreads();
    if (t < 36) {
        float sum = 0.f, mx = -1e30f;
        #pragma unroll
        for (int c = 0; c < 64; c++) { float v = sh[c*36+t]; sum += v; mx = fmaxf(mx, v); }
        m2[t] = sum*(1.f/64.f); x2[t] = mx;
    }
    __syncthreads();
    if (t < 36) {
        int sy = t/6, sx = t%6;
        float a = 0.f;
        for (int ky = 0; ky < 7; ky++) {
            int iy = sy + ky - 3; if (iy < 0 || iy >= 6) continue;
            for (int kx = 0; kx < 7; kx++) {
                int ix = sx + kx - 3; if (ix < 0 || ix >= 6) continue;
                a += spw[ky*7+kx]*m2[iy*6+ix] + spw[49+ky*7+kx]*x2[iy*6+ix];
            }
        }
        ss[t] = 1.f/(1.f+expf(-a));
    }
    __syncthreads();
    for (int o = t; o < 2304; o += 256) {
        int c = o/36, s = o%36;
        g_tok[((size_t)n*36 + s)*64 + c] = sh[o]*ss[s];
    }
}

// ---------------- generic SGEMM: C(M,N) = act(A(M,K) @ W(N,K)^T + bias) ----------------
template<int RELU, int BIAS>
__global__ void k_gemm(const float* __restrict__ A, const float* __restrict__ W,
                       const float* __restrict__ bias, float* __restrict__ C,
                       int M, int N, int K) {
    __shared__ float As[16][64], Ws[16][64];
    int m0 = blockIdx.x*64, n0 = blockIdx.y*64;
    int tid = threadIdx.x;
    int lr = tid >> 2, lk = (tid & 3) << 2;
    int tx = tid & 15, ty = tid >> 4;
    float acc[4][4] = {};
    for (int k0 = 0; k0 < K; k0 += 16) {
        float4 a = *(const float4*)(A + (size_t)(m0+lr)*K + k0 + lk);
        float4 w = *(const float4*)(W + (size_t)(n0+lr)*K + k0 + lk);
        As[lk  ][lr] = a.x; As[lk+1][lr] = a.y; As[lk+2][lr] = a.z; As[lk+3][lr] = a.w;
        Ws[lk  ][lr] = w.x; Ws[lk+1][lr] = w.y; Ws[lk+2][lr] = w.z; Ws[lk+3][lr] = w.w;
        __syncthreads();
        #pragma unroll
        for (int kk = 0; kk < 16; kk++) {
            float4 av = *(const float4*)&As[kk][tx<<2];
            float4 wv = *(const float4*)&Ws[kk][ty<<2];
            float ar[4] = {av.x, av.y, av.z, av.w};
            float wr[4] = {wv.x, wv.y, wv.z, wv.w};
            #pragma unroll
            for (int i = 0; i < 4; i++)
                #pragma unroll
                for (int j = 0; j < 4; j++)
                    acc[i][j] += ar[i]*wr[j];
        }
        __syncthreads();
    }
    #pragma unroll
    for (int i = 0; i < 4; i++) {
        int m = m0 + (tx<<2) + i;
        #pragma unroll
        for (int j = 0; j < 4; j++) {
            int nn = n0 + (ty<<2) + j;
            float v = acc[i][j];
            if (BIAS) v += bias[nn];
            if (RELU) v = fmaxf(v, 0.f);
            C[(size_t)m*N + nn] = v;
        }
    }
}

// ---------------- per-(n,head) attention over 36 tokens ----------------
__global__ void k_attn() {
    int head = blockIdx.x, n = blockIdx.y, t = threadIdx.x;
    __shared__ float qs[36*16], ks[36*16], vs[36*16];
    for (int idx = t; idx < 576; idx += 64) {
        int s = idx >> 4, d = idx & 15;
        const float* base = g_qkv + ((size_t)n*36 + s)*192 + head*16 + d;
        qs[idx] = base[0]; ks[idx] = base[64]; vs[idx] = base[128];
    }
    __syncthreads();
    if (t < 36) {
        float qr[16];
        #pragma unroll
        for (int d = 0; d < 16; d++) qr[d] = qs[t*16+d];
        float sc[36]; float mx = -1e30f;
        #pragma unroll
        for (int s2 = 0; s2 < 36; s2++) {
            float a = 0.f;
            #pragma unroll
            for (int d = 0; d < 16; d++) a += qr[d]*ks[s2*16+d];
            a *= 0.25f;
            sc[s2] = a; mx = fmaxf(mx, a);
        }
        float sum = 0.f;
        #pragma unroll
        for (int s2 = 0; s2 < 36; s2++) { float e = expf(sc[s2]-mx); sc[s2] = e; sum += e; }
        float inv = 1.f/sum;
        #pragma unroll
        for (int d = 0; d < 16; d++) {
            float o = 0.f;
            #pragma unroll
            for (int s2 = 0; s2 < 36; s2++) o += sc[s2]*vs[s2*16+d];
            g_attn[((size_t)n*36 + t)*64 + head*16 + d] = o*inv;
        }
    }
}

// ---------------- proj + residual, writes (N,64,36) layout for FC ----------------
__global__ void k_proj(const float* __restrict__ projw, const float* __restrict__ projb) {
    __shared__ float at[2304];
    int n = blockIdx.x, t = threadIdx.x;
    for (int o = t; o < 2304; o += 256) at[o] = g_attn[(size_t)n*2304 + o];
    __syncthreads();
    for (int o = t; o < 2304; o += 256) {
        int c = o/36, s = o%36;
        const float4* pw = (const float4*)(projw + c*64);
        const float4* av = (const float4*)(at + s*64);
        float a = 0.f;
        #pragma unroll
        for (int j = 0; j < 16; j++) {
            float4 p = pw[j], q = av[j];
            a += p.x*q.x + p.y*q.y + p.z*q.z + p.w*q.w;
        }
        g_h2[(size_t)n*2304 + o] = g_tok[((size_t)n*36 + s)*64 + c] + a + projb[c];
    }
}

// ---------------- masked GRU scan: 32 independent batch chains ----------------
__global__ void k_gru(const float* __restrict__ done, const float* __restrict__ h0,
                      const float* __restrict__ bhh) {
    int b = blockIdx.x, t = threadIdx.x;
    __shared__ float h_s[128], hm_s[128], gh_s[384];
    h_s[t] = h0[b*128 + t];
    __syncthreads();
    for (int step = 0; step < 64; step++) {
        float dt = done[step*32 + b];
        hm_s[t] = (1.f - dt)*h_s[t];
        __syncthreads();
        if (t < 96) {
            int g = t*4;
            float a0 = bhh[g], a1 = bhh[g+1], a2 = bhh[g+2], a3 = bhh[g+3];
            #pragma unroll 8
            for (int k = 0; k < 128; k++) {
                float hm = hm_s[k];
                float4 w = *(const float4*)(g_whht + k*384 + g);
                a0 += w.x*hm; a1 += w.y*hm; a2 += w.z*hm; a3 += w.w*hm;
            }
            gh_s[g] = a0; gh_s[g+1] = a1; gh_s[g+2] = a2; gh_s[g+3] = a3;
        }
        __syncthreads();
        int row = step*32 + b;
        float xr = g_gx[(size_t)row*384 + t];
        float xz = g_gx[(size_t)row*384 + 128 + t];
        float xn = g_gx[(size_t)row*384 + 256 + t];
        float hr = gh_s[t], hz = gh_s[128+t], hn = gh_s[256+t];
        float rg = 1.f/(1.f+expf(-(xr+hr)));
        float zg = 1.f/(1.f+expf(-(xz+hz)));
        float ng = tanhf(xn + rg*hn);
        float hnew = (1.f-zg)*ng + zg*hm_s[t];
        h_s[t] = hnew;
        g_hid[(size_t)row*128 + t] = hnew;
        __syncthreads();
    }
}

// ---------------- critic head: (2048,128) @ crw^T + crb ----------------
__global__ void k_critic(const float* __restrict__ crw, const float* __restrict__ crb,
                         float* __restrict__ out) {
    int warp = threadIdx.x >> 5, lane = threadIdx.x & 31;
    int row = blockIdx.x*8 + warp;
    const float4* h4 = (const float4*)(g_hid + (size_t)row*128);
    float4 hv = h4[lane];
    float4 wv = ((const float4*)crw)[lane];
    float s = hv.x*wv.x + hv.y*wv.y + hv.z*wv.z + hv.w*wv.w;
    #pragma unroll
    for (int o = 16; o; o >>= 1) s += __shfl_down_sync(0xffffffffu, s, o);
    if (lane == 0) out[row] = s + crb[0];
}

// ---------------- launch ----------------
extern "C" void kernel_launch(void* const* d_in, const int* in_sizes, int n_in,
                              void* d_out, int out_size) {
    const float* x    = (const float*)d_in[0];
    const float* done = (const float*)d_in[1];
    const float* gru0 = (const float*)d_in[2];
    const float* c1w  = (const float*)d_in[3];
    const float* c1b  = (const float*)d_in[4];
    const float* c2w  = (const float*)d_in[5];
    const float* c2b  = (const float*)d_in[6];
    const float* c3w  = (const float*)d_in[7];
    const float* c3b  = (const float*)d_in[8];
    const float* fc1w = (const float*)d_in[9];
    const float* fc2w = (const float*)d_in[10];
    const float* spw  = (const float*)d_in[11];
    const float* qkvw = (const float*)d_in[12];
    const float* projw= (const float*)d_in[13];
    const float* projb= (const float*)d_in[14];
    const float* fcw  = (const float*)d_in[15];
    const float* fcb  = (const float*)d_in[16];
    const float* wih  = (const float*)d_in[17];
    const float* whh  = (const float*)d_in[18];
    const float* bih  = (const float*)d_in[19];
    const float* bhh  = (const float*)d_in[20];
    const float* crw  = (const float*)d_in[21];
    const float* crb  = (const float*)d_in[22];
    float* out = (float*)d_out;

    float *p_tok, *p_qkv, *p_h2, *p_feat, *p_gx;
    cudaGetSymbolAddress((void**)&p_tok,  g_tok);
    cudaGetSymbolAddress((void**)&p_qkv,  g_qkv);
    cudaGetSymbolAddress((void**)&p_h2,   g_h2);
    cudaGetSymbolAddress((void**)&p_feat, g_feat);
    cudaGetSymbolAddress((void**)&p_gx,   g_gx);

    // prep (ordered so the profiled launch lands on k_conv1)
    k_transpose<<<(32*256 + 255)/256, 256>>>(c1w, 32, 256, 0);
    k_transpose<<<(64*512 + 255)/256, 256>>>(c2w, 64, 512, 1);
    k_transpose<<<(384*128 + 255)/256, 256>>>(whh, 384, 128, 3);

    // conv backbone
    k_conv1<<<dim3(7, 2048), 128>>>(x, c1b);
    k_transpose<<<(64*576 + 255)/256, 256>>>(c3w, 64, 576, 2);
    k_conv2<<<dim3(4, 2048), 128>>>(c2b);
    k_conv3<<<2048, 288>>>(c3b);

    // CBAM
    k_chatt<<<2048, 64>>>(fc1w, fc2w);
    k_spatial<<<2048, 256>>>(spw);

    // spatial self-attention
    k_gemm<0,0><<<dim3(73728/64, 192/64), 256>>>(p_tok, qkvw, (const float*)0, p_qkv, 73728, 192, 64);
    k_attn<<<dim3(4, 2048), 64>>>();
    k_proj<<<2048, 256>>>(projw, projb);

    // FC + GRU input gates
    k_gemm<1,1><<<dim3(2048/64, 256/64), 256>>>(p_h2, fcw, fcb, p_feat, 2048, 256, 2304);
    k_gemm<0,1><<<dim3(2048/64, 384/64), 256>>>(p_feat, wih, bih, p_gx, 2048, 384, 256);

    // GRU scan + critic
    k_gru<<<32, 128>>>(done, gru0, bhh);
    k_critic<<<2048/8, 256>>>(crw, crb, out);
}